// round 10
// baseline (speedup 1.0000x reference)
#include <cuda_runtime.h>
#include <math.h>

#define NB 8
#define NT 4096
#define ND 512
#define NSER (NB * ND)   // 4096 series
#define TOPK 7
#define TCHUNK 128

// Per-series coefficients (k, 2Re, 2Im)
__device__ float4 g_coef[NSER * TOPK];

// ---------------------------------------------------------------------------
// Kernel 1: radix-16 Stockham FFT (N=4096, 3 stages), 2 real series packed
//           per complex FFT, loading DIRECTLY from (b,t,d) layout:
//           Z[t] = x[b,t,2e] + i*x[b,t,2e+1]  (one float2 per t).
//           Top-7 per series: two halves in parallel on warp groups 0-3/4-7,
//           cached per-thread bests, 1 named barrier per iteration.
// ---------------------------------------------------------------------------
__device__ __forceinline__ float2 cmul(float2 a, float2 b) {
    return make_float2(a.x * b.x - a.y * b.y, a.x * b.y + a.y * b.x);
}

__device__ __forceinline__ void dft4(float2& A, float2& B, float2& C, float2& D) {
    float2 apc  = make_float2(A.x + C.x, A.y + C.y);
    float2 amc  = make_float2(A.x - C.x, A.y - C.y);
    float2 bpd  = make_float2(B.x + D.x, B.y + D.y);
    float2 jbmd = make_float2(-(B.y - D.y), B.x - D.x);   // i*(B-D)
    A = make_float2(apc.x + bpd.x, apc.y + bpd.y);
    B = make_float2(amc.x - jbmd.x, amc.y - jbmd.y);
    C = make_float2(apc.x - bpd.x, apc.y - bpd.y);
    D = make_float2(amc.x + jbmd.x, amc.y + jbmd.y);
}

#define C8f  0.70710678118654752f
#define C16f 0.92387953251128676f
#define S16f 0.38268343236508977f

// In-place 16-point DFT. After this, slot (4*u1 + u2) holds X[u1 + 4*u2].
__device__ __forceinline__ void dft16(float2* a) {
#pragma unroll
    for (int r2 = 0; r2 < 4; r2++)
        dft4(a[r2], a[r2 + 4], a[r2 + 8], a[r2 + 12]);
    a[5]  = cmul(a[5],  make_float2( C16f, -S16f));
    a[6]  = cmul(a[6],  make_float2( C8f,  -C8f ));
    a[7]  = cmul(a[7],  make_float2( S16f, -C16f));
    a[9]  = cmul(a[9],  make_float2( C8f,  -C8f ));
    a[10] = make_float2(a[10].y, -a[10].x);
    a[11] = cmul(a[11], make_float2(-C8f,  -C8f ));
    a[13] = cmul(a[13], make_float2( S16f, -C16f));
    a[14] = cmul(a[14], make_float2(-C8f,  -C8f ));
    a[15] = cmul(a[15], make_float2(-C16f,  S16f));
#pragma unroll
    for (int u1 = 0; u1 < 4; u1++)
        dft4(a[4 * u1 + 0], a[4 * u1 + 1], a[4 * u1 + 2], a[4 * u1 + 3]);
}

template<int S, int SH, bool TW>
__device__ __forceinline__ void fft_stage(float2* buf, int i) {
    float2 a[16];
#pragma unroll
    for (int r = 0; r < 16; r++) {
        int idx = i + 256 * r;
        a[r] = buf[idx + (idx >> 4)];
    }
    __syncthreads();
    dft16(a);
    int q = i & (S - 1);
    int p = i >> SH;
    if (TW) {
        float sw, cw;
        sincospif((float)(S * p) * (1.0f / 2048.0f), &sw, &cw);
        float2 w1 = make_float2(cw, -sw);
        float2 wu = w1;
#pragma unroll
        for (int u = 1; u < 16; u++) {
            int s = ((u & 3) << 2) | (u >> 2);
            a[s] = cmul(a[s], wu);
            wu = cmul(wu, w1);
        }
    }
    int ob = q + ((p * S) << 4);
#pragma unroll
    for (int u = 0; u < 16; u++) {
        int s = ((u & 3) << 2) | (u >> 2);
        int idx = ob + S * u;
        buf[idx + (idx >> 4)] = a[s];
    }
    __syncthreads();
}

__device__ __forceinline__ void grp_bar(int id) {
    asm volatile("bar.sync %0, %1;" :: "r"(id), "r"(128) : "memory");
}

// Top-7 over one half-series, executed by a 128-thread warp group.
// gtid in [0,128); k = gtid + 128*r, r in [0,16).
// Per-thread best cached; amp[k] is only re-read by its owning thread, so
// each iteration needs exactly one group barrier (wm slots parity-buffered).
__device__ __forceinline__ void topk_group(float* amp, const float2* buf,
                                           unsigned long long* wm,
                                           int gtid, int gwid, int lane,
                                           int series, bool halfB, int barid) {
    unsigned long long myBest = 0ull;
#pragma unroll
    for (int r = 0; r < 16; r++) {
        int k = gtid + 128 * r;
        unsigned long long pk =
            ((unsigned long long)__float_as_uint(amp[k]) << 32) | (unsigned)(4095 - k);
        if (pk > myBest) myBest = pk;
    }
    for (int it = 0; it < TOPK; it++) {
        unsigned long long best = myBest;
#pragma unroll
        for (int off = 16; off; off >>= 1) {
            unsigned long long o = __shfl_xor_sync(0xffffffffu, best, off);
            if (o > best) best = o;
        }
        unsigned long long* ws = wm + (it & 1) * 4;
        if (lane == 0) ws[gwid] = best;
        grp_bar(barid);
        unsigned long long bb = ws[0];
#pragma unroll
        for (int w = 1; w < 4; w++) if (ws[w] > bb) bb = ws[w];
        int kstar = 4095 - (int)(unsigned)(bb & 0xffffffffull);
        if (gtid == (kstar & 127)) {
            amp[kstar] = 0.0f;    // remove winner (only this thread reads it)
            float2 zk = buf[kstar + (kstar >> 4)];
            int n = NT - kstar;
            float2 zn = buf[n + (n >> 4)];
            float re2, im2;   // 2*Re(X), 2*Im(X)
            if (!halfB) { re2 = zk.x + zn.x; im2 = zk.y - zn.y; }
            else        { re2 = zk.y + zn.y; im2 = zn.x - zk.x; }
            g_coef[series * TOPK + it] = make_float4((float)kstar, re2, im2, 0.0f);
            // recompute this thread's cached best
            myBest = 0ull;
#pragma unroll
            for (int r = 0; r < 16; r++) {
                int k = gtid + 128 * r;
                unsigned long long pk =
                    ((unsigned long long)__float_as_uint(amp[k]) << 32) | (unsigned)(4095 - k);
                if (pk > myBest) myBest = pk;
            }
        }
    }
}

extern __shared__ float2 sdyn[];

__global__ __launch_bounds__(256) void fft_topk_kernel(const float* __restrict__ x) {
    float2* buf  = sdyn;                     // 4352 float2 (padded 4096)
    float*  ampA = (float*)(sdyn + 4352);    // 2048 floats
    float*  ampB = ampA + 2048;              // 2048 floats
    __shared__ unsigned long long wmax[16];

    int tid = threadIdx.x;
    int b = blockIdx.x >> 8;
    int e = blockIdx.x & 255;
    int series0 = b * ND + 2 * e;

    // Pack two adjacent-d series straight from (b,t,d) layout:
    // Z[t] = x[b,t,2e] + i*x[b,t,2e+1]  — one float2, stride ND/2 float2 per t.
    const float2* xp = (const float2*)x + (size_t)b * NT * (ND / 2) + e;
#pragma unroll
    for (int r = 0; r < 16; r++) {
        int idx = tid + 256 * r;
        float2 z = __ldg(&xp[(size_t)idx * (ND / 2)]);
        buf[idx + (idx >> 4)] = z;
    }
    __syncthreads();

    fft_stage<1,   0, true >(buf, tid);
    fft_stage<16,  4, true >(buf, tid);
    fft_stage<256, 8, false>(buf, tid);

    // Unpack amplitudes (x4, ranking-invariant) for k in [0, 2048)
    // X_a[k] = (Z[k]+conj(Z[N-k]))/2, X_b[k] = -i(Z[k]-conj(Z[N-k]))/2
#pragma unroll
    for (int r = 0; r < 8; r++) {
        int k = tid + 256 * r;
        if (k == 0) {
            ampA[0] = 0.0f; ampB[0] = 0.0f;   // exclude DC
        } else {
            float2 zk = buf[k + (k >> 4)];
            int n = NT - k;
            float2 zn = buf[n + (n >> 4)];
            float ra = zk.x + zn.x, ia = zk.y - zn.y;
            float rb = zk.y + zn.y, ib = zn.x - zk.x;
            ampA[k] = ra * ra + ia * ia;
            ampB[k] = rb * rb + ib * ib;
        }
    }
    __syncthreads();

    int lane = tid & 31, wid = tid >> 5;
    if (wid < 4)
        topk_group(ampA, buf, wmax,     tid,       wid,     lane, series0,     false, 1);
    else
        topk_group(ampB, buf, wmax + 8, tid - 128, wid - 4, lane, series0 + 1, true,  2);
}

// ---------------------------------------------------------------------------
// Kernel 2: reconstruction via Chebyshev recurrence
// y_j[t] = 2Re_j*cos(th) - 2Im_j*sin(th), th = 2*pi*k_j*t/4096
// y_j[t+1] = 2*cos(w_j)*y_j[t] - y_j[t-1]
// ---------------------------------------------------------------------------
__global__ __launch_bounds__(256) void recon_kernel(float* __restrict__ out) {
    int d  = blockIdx.x * 256 + threadIdx.x;   // gridDim.x = 2
    int b  = blockIdx.z;
    int t0 = blockIdx.y * TCHUNK;
    int series = b * ND + d;

    float ycur[TOPK], yprev[TOPK], twocw[TOPK];
#pragma unroll
    for (int j = 0; j < TOPK; j++) {
        float4 cf = __ldg(&g_coef[series * TOPK + j]);
        int k = (int)cf.x;
        float c2 = cf.y, s2 = cf.z;
        int m0 = (k * t0) & 4095;          // exact angle reduction mod 2*pi
        int m1 = (m0 - k) & 4095;          // angle at t0-1
        float ss, cc;
        sincospif((float)m0 * (1.0f / 2048.0f), &ss, &cc);
        ycur[j]  = c2 * cc - s2 * ss;
        sincospif((float)m1 * (1.0f / 2048.0f), &ss, &cc);
        yprev[j] = c2 * cc - s2 * ss;
        sincospif((float)k * (1.0f / 2048.0f), &ss, &cc);
        twocw[j] = 2.0f * cc;
    }
    float* op = out + ((size_t)b * NT + t0) * ND + d;
#pragma unroll 4
    for (int tt = 0; tt < TCHUNK; tt++) {
        float acc = 0.0f;
#pragma unroll
        for (int j = 0; j < TOPK; j++)
            acc += ycur[j];
        op[(size_t)tt * ND] = acc;
#pragma unroll
        for (int j = 0; j < TOPK; j++) {
            float yn = twocw[j] * ycur[j] - yprev[j];
            yprev[j] = ycur[j];
            ycur[j]  = yn;
        }
    }
}

// ---------------------------------------------------------------------------
extern "C" void kernel_launch(void* const* d_in, const int* in_sizes, int n_in,
                              void* d_out, int out_size) {
    const float* x = (const float*)d_in[0];
    float* out = (float*)d_out;

    size_t shmem = 4352 * sizeof(float2) + 4096 * sizeof(float);  // 51200 B
    cudaFuncSetAttribute(fft_topk_kernel,
                         cudaFuncAttributeMaxDynamicSharedMemorySize, (int)shmem);
    fft_topk_kernel<<<NSER / 2, 256, shmem>>>(x);

    dim3 rg(ND / 256, NT / TCHUNK, NB);
    recon_kernel<<<rg, 256>>>(out);
}

// round 13
// speedup vs baseline: 1.4929x; 1.4929x over previous
#include <cuda_runtime.h>
#include <math.h>

#define NB 8
#define NT 4096
#define ND 512
#define NSER (NB * ND)   // 4096 series
#define TOPK 7
#define TCHUNK 64

// Scratch: transposed input (b, d, t) and per-series coefficients
__device__ float  g_xt[(size_t)NSER * NT];        // 64 MB
__device__ float4 g_coef[NSER * TOPK];

// ---------------------------------------------------------------------------
// Kernel 1: transpose (b, t, d) -> (b, d, t); 128t x 32d tile, 4 float4 each way
// ---------------------------------------------------------------------------
__global__ __launch_bounds__(256) void transpose_kernel(const float* __restrict__ in) {
    __shared__ float tile[128][33];
    int b  = blockIdx.z;
    int t0 = blockIdx.x * 128;
    int d0 = blockIdx.y * 32;
    int tx = threadIdx.x;   // 0..7
    int ty = threadIdx.y;   // 0..31

    const float* ip = in + ((size_t)b * NT + t0 + ty) * ND + d0 + tx * 4;
    float4 v[4];
#pragma unroll
    for (int i = 0; i < 4; i++)
        v[i] = *(const float4*)(ip + (size_t)(32 * i) * ND);
#pragma unroll
    for (int i = 0; i < 4; i++) {
        tile[ty + 32 * i][tx * 4 + 0] = v[i].x;
        tile[ty + 32 * i][tx * 4 + 1] = v[i].y;
        tile[ty + 32 * i][tx * 4 + 2] = v[i].z;
        tile[ty + 32 * i][tx * 4 + 3] = v[i].w;
    }
    __syncthreads();
    float* op = g_xt + ((size_t)b * ND + d0 + ty) * NT + t0 + tx * 4;
#pragma unroll
    for (int i = 0; i < 4; i++) {
        float4 w = make_float4(tile[tx * 4 + 32 * i + 0][ty],
                               tile[tx * 4 + 32 * i + 1][ty],
                               tile[tx * 4 + 32 * i + 2][ty],
                               tile[tx * 4 + 32 * i + 3][ty]);
        *(float4*)(op + 32 * i) = w;
    }
}

// ---------------------------------------------------------------------------
// Kernel 2: radix-16 Stockham FFT (N=4096, 3 stages), 2 real series packed
//           per complex FFT, + top-7 per series (two halves in parallel on
//           warp groups 0-3 / 4-7, cached bests, 1 named barrier/iteration)
// ---------------------------------------------------------------------------
__device__ __forceinline__ float2 cmul(float2 a, float2 b) {
    return make_float2(a.x * b.x - a.y * b.y, a.x * b.y + a.y * b.x);
}

__device__ __forceinline__ void dft4(float2& A, float2& B, float2& C, float2& D) {
    float2 apc  = make_float2(A.x + C.x, A.y + C.y);
    float2 amc  = make_float2(A.x - C.x, A.y - C.y);
    float2 bpd  = make_float2(B.x + D.x, B.y + D.y);
    float2 jbmd = make_float2(-(B.y - D.y), B.x - D.x);   // i*(B-D)
    A = make_float2(apc.x + bpd.x, apc.y + bpd.y);
    B = make_float2(amc.x - jbmd.x, amc.y - jbmd.y);
    C = make_float2(apc.x - bpd.x, apc.y - bpd.y);
    D = make_float2(amc.x + jbmd.x, amc.y + jbmd.y);
}

#define C8f  0.70710678118654752f
#define C16f 0.92387953251128676f
#define S16f 0.38268343236508977f

// In-place 16-point DFT. After this, slot (4*u1 + u2) holds X[u1 + 4*u2].
__device__ __forceinline__ void dft16(float2* a) {
#pragma unroll
    for (int r2 = 0; r2 < 4; r2++)
        dft4(a[r2], a[r2 + 4], a[r2 + 8], a[r2 + 12]);
    a[5]  = cmul(a[5],  make_float2( C16f, -S16f));
    a[6]  = cmul(a[6],  make_float2( C8f,  -C8f ));
    a[7]  = cmul(a[7],  make_float2( S16f, -C16f));
    a[9]  = cmul(a[9],  make_float2( C8f,  -C8f ));
    a[10] = make_float2(a[10].y, -a[10].x);
    a[11] = cmul(a[11], make_float2(-C8f,  -C8f ));
    a[13] = cmul(a[13], make_float2( S16f, -C16f));
    a[14] = cmul(a[14], make_float2(-C8f,  -C8f ));
    a[15] = cmul(a[15], make_float2(-C16f,  S16f));
#pragma unroll
    for (int u1 = 0; u1 < 4; u1++)
        dft4(a[4 * u1 + 0], a[4 * u1 + 1], a[4 * u1 + 2], a[4 * u1 + 3]);
}

template<int S, int SH, bool TW>
__device__ __forceinline__ void fft_stage(float2* buf, int i) {
    float2 a[16];
#pragma unroll
    for (int r = 0; r < 16; r++) {
        int idx = i + 256 * r;
        a[r] = buf[idx + (idx >> 4)];
    }
    __syncthreads();
    dft16(a);
    int q = i & (S - 1);
    int p = i >> SH;
    if (TW) {
        float sw, cw;
        sincospif((float)(S * p) * (1.0f / 2048.0f), &sw, &cw);
        float2 w1 = make_float2(cw, -sw);
        // 4 independent twiddle chains stepped by w4 (depth <= 4 vs 14 serial)
        float2 w2 = cmul(w1, w1);
        float2 w3 = cmul(w2, w1);
        float2 w4 = cmul(w2, w2);
        float2 c1 = w1, c2 = w2, c3 = w3, c0 = w4;
#pragma unroll
        for (int g = 0; g < 4; g++) {
            int u1 = 4 * g + 1, u2 = 4 * g + 2, u3 = 4 * g + 3, u4 = 4 * g + 4;
            // slot holding X[u] is ((u&3)<<2)|(u>>2)
            a[((u1 & 3) << 2) | (u1 >> 2)] = cmul(a[((u1 & 3) << 2) | (u1 >> 2)], c1);
            a[((u2 & 3) << 2) | (u2 >> 2)] = cmul(a[((u2 & 3) << 2) | (u2 >> 2)], c2);
            a[((u3 & 3) << 2) | (u3 >> 2)] = cmul(a[((u3 & 3) << 2) | (u3 >> 2)], c3);
            if (u4 < 16)
                a[((u4 & 3) << 2) | (u4 >> 2)] = cmul(a[((u4 & 3) << 2) | (u4 >> 2)], c0);
            if (g < 3) {
                c1 = cmul(c1, w4);
                c2 = cmul(c2, w4);
                c3 = cmul(c3, w4);
                c0 = cmul(c0, w4);
            }
        }
    }
    int ob = q + ((p * S) << 4);
#pragma unroll
    for (int u = 0; u < 16; u++) {
        int s = ((u & 3) << 2) | (u >> 2);
        int idx = ob + S * u;
        buf[idx + (idx >> 4)] = a[s];
    }
    __syncthreads();
}

__device__ __forceinline__ void grp_bar(int id) {
    asm volatile("bar.sync %0, %1;" :: "r"(id), "r"(128) : "memory");
}

// Top-7 over one half-series, executed by a 128-thread warp group.
// gtid in [0,128); k = gtid + 128*r, r in [0,16).
// Per-thread best cached; amp[k] is only re-read by its owning thread, so
// each iteration needs exactly one group barrier (wm slots parity-buffered).
__device__ __forceinline__ void topk_group(float* amp, const float2* buf,
                                           unsigned long long* wm,
                                           int gtid, int gwid, int lane,
                                           int series, bool halfB, int barid) {
    unsigned long long myBest = 0ull;
#pragma unroll
    for (int r = 0; r < 16; r++) {
        int k = gtid + 128 * r;
        unsigned long long pk =
            ((unsigned long long)__float_as_uint(amp[k]) << 32) | (unsigned)(4095 - k);
        if (pk > myBest) myBest = pk;
    }
    for (int it = 0; it < TOPK; it++) {
        unsigned long long best = myBest;
#pragma unroll
        for (int off = 16; off; off >>= 1) {
            unsigned long long o = __shfl_xor_sync(0xffffffffu, best, off);
            if (o > best) best = o;
        }
        unsigned long long* ws = wm + (it & 1) * 4;
        if (lane == 0) ws[gwid] = best;
        grp_bar(barid);
        unsigned long long bb = ws[0];
#pragma unroll
        for (int w = 1; w < 4; w++) if (ws[w] > bb) bb = ws[w];
        int kstar = 4095 - (int)(unsigned)(bb & 0xffffffffull);
        if (gtid == (kstar & 127)) {
            amp[kstar] = 0.0f;    // remove winner (only this thread reads it)
            float2 zk = buf[kstar + (kstar >> 4)];
            int n = NT - kstar;
            float2 zn = buf[n + (n >> 4)];
            float re2, im2;   // 2*Re(X), 2*Im(X)
            if (!halfB) { re2 = zk.x + zn.x; im2 = zk.y - zn.y; }
            else        { re2 = zk.y + zn.y; im2 = zn.x - zk.x; }
            g_coef[series * TOPK + it] = make_float4((float)kstar, re2, im2, 0.0f);
            // recompute this thread's cached best
            myBest = 0ull;
#pragma unroll
            for (int r = 0; r < 16; r++) {
                int k = gtid + 128 * r;
                unsigned long long pk =
                    ((unsigned long long)__float_as_uint(amp[k]) << 32) | (unsigned)(4095 - k);
                if (pk > myBest) myBest = pk;
            }
        }
    }
}

extern __shared__ float2 sdyn[];

__global__ __launch_bounds__(256) void fft_topk_kernel() {
    float2* buf  = sdyn;                     // 4352 float2 (padded 4096)
    float*  ampA = (float*)(sdyn + 4352);    // 2048 floats
    float*  ampB = ampA + 2048;              // 2048 floats
    __shared__ unsigned long long wmax[16];

    int tid = threadIdx.x;
    int b = blockIdx.x >> 8;
    int e = blockIdx.x & 255;
    int series0 = b * ND + 2 * e;
    const float4* x04 = (const float4*)(g_xt + (size_t)series0 * NT);
    const float4* x14 = (const float4*)(g_xt + (size_t)(series0 + 1) * NT);

    // Pack two real series: Z = x0 + i*x1 (float4 coalesced global reads)
#pragma unroll
    for (int r = 0; r < 4; r++) {
        float4 va = x04[tid + 256 * r];
        float4 vb = x14[tid + 256 * r];
        int i0 = 4 * (tid + 256 * r);
        buf[(i0 + 0) + ((i0 + 0) >> 4)] = make_float2(va.x, vb.x);
        buf[(i0 + 1) + ((i0 + 1) >> 4)] = make_float2(va.y, vb.y);
        buf[(i0 + 2) + ((i0 + 2) >> 4)] = make_float2(va.z, vb.z);
        buf[(i0 + 3) + ((i0 + 3) >> 4)] = make_float2(va.w, vb.w);
    }
    __syncthreads();

    fft_stage<1,   0, true >(buf, tid);
    fft_stage<16,  4, true >(buf, tid);
    fft_stage<256, 8, false>(buf, tid);

    // Unpack amplitudes (x4, ranking-invariant) for k in [0, 2048)
    // X_a[k] = (Z[k]+conj(Z[N-k]))/2, X_b[k] = -i(Z[k]-conj(Z[N-k]))/2
#pragma unroll
    for (int r = 0; r < 8; r++) {
        int k = tid + 256 * r;
        if (k == 0) {
            ampA[0] = 0.0f; ampB[0] = 0.0f;   // exclude DC
        } else {
            float2 zk = buf[k + (k >> 4)];
            int n = NT - k;
            float2 zn = buf[n + (n >> 4)];
            float ra = zk.x + zn.x, ia = zk.y - zn.y;
            float rb = zk.y + zn.y, ib = zn.x - zk.x;
            ampA[k] = ra * ra + ia * ia;
            ampB[k] = rb * rb + ib * ib;
        }
    }
    __syncthreads();

    int lane = tid & 31, wid = tid >> 5;
    if (wid < 4)
        topk_group(ampA, buf, wmax,     tid,       wid,     lane, series0,     false, 1);
    else
        topk_group(ampB, buf, wmax + 8, tid - 128, wid - 4, lane, series0 + 1, true,  2);
}

// ---------------------------------------------------------------------------
// Kernel 3: reconstruction via Chebyshev recurrence
// y_j[t] = 2Re_j*cos(th) - 2Im_j*sin(th), th = 2*pi*k_j*t/4096
// y_j[t+1] = 2*cos(w_j)*y_j[t] - y_j[t-1]
// ---------------------------------------------------------------------------
__global__ __launch_bounds__(256) void recon_kernel(float* __restrict__ out) {
    int d  = blockIdx.x * 256 + threadIdx.x;   // gridDim.x = 2
    int b  = blockIdx.z;
    int t0 = blockIdx.y * TCHUNK;
    int series = b * ND + d;

    float ycur[TOPK], yprev[TOPK], twocw[TOPK];
#pragma unroll
    for (int j = 0; j < TOPK; j++) {
        float4 cf = __ldg(&g_coef[series * TOPK + j]);
        int k = (int)cf.x;
        float c2 = cf.y, s2 = cf.z;
        int m0 = (k * t0) & 4095;          // exact angle reduction mod 2*pi
        int m1 = (m0 - k) & 4095;          // angle at t0-1
        float ss, cc;
        sincospif((float)m0 * (1.0f / 2048.0f), &ss, &cc);
        ycur[j]  = c2 * cc - s2 * ss;
        sincospif((float)m1 * (1.0f / 2048.0f), &ss, &cc);
        yprev[j] = c2 * cc - s2 * ss;
        sincospif((float)k * (1.0f / 2048.0f), &ss, &cc);
        twocw[j] = 2.0f * cc;
    }
    float* op = out + ((size_t)b * NT + t0) * ND + d;
#pragma unroll 4
    for (int tt = 0; tt < TCHUNK; tt++) {
        float acc = 0.0f;
#pragma unroll
        for (int j = 0; j < TOPK; j++)
            acc += ycur[j];
        op[(size_t)tt * ND] = acc;
#pragma unroll
        for (int j = 0; j < TOPK; j++) {
            float yn = twocw[j] * ycur[j] - yprev[j];
            yprev[j] = ycur[j];
            ycur[j]  = yn;
        }
    }
}

// ---------------------------------------------------------------------------
extern "C" void kernel_launch(void* const* d_in, const int* in_sizes, int n_in,
                              void* d_out, int out_size) {
    const float* x = (const float*)d_in[0];
    float* out = (float*)d_out;

    dim3 tb(8, 32);
    dim3 tg(NT / 128, ND / 32, NB);
    transpose_kernel<<<tg, tb>>>(x);

    size_t shmem = 4352 * sizeof(float2) + 4096 * sizeof(float);  // 51200 B
    cudaFuncSetAttribute(fft_topk_kernel,
                         cudaFuncAttributeMaxDynamicSharedMemorySize, (int)shmem);
    fft_topk_kernel<<<NSER / 2, 256, shmem>>>();

    dim3 rg(ND / 256, NT / TCHUNK, NB);
    recon_kernel<<<rg, 256>>>(out);
}